// round 1
// baseline (speedup 1.0000x reference)
#include <cuda_runtime.h>
#include <math.h>

#define Bn 16
#define Sn 512
#define Dn 768
#define Hn 8
#define DKn 96

// -------- static scratch (no runtime allocation allowed) --------
__device__ float g_q[Bn * Sn * Dn];
__device__ float g_k[Bn * Sn * Dn];
__device__ float g_ax[Bn * Sn * Dn];
__device__ float g_h0[Bn * Sn * Dn];
__device__ float g_h1[Bn * Sn * Dn];
__device__ float g_denom[Bn * Sn];
__device__ float g_pool[Bn * 2 * Dn];
__device__ float g_gc[Bn * Dn];
__device__ float g_gate[Bn * Dn];

// ================= GEMM: C[bz] = act((A[bz] @ W[bz] + bias) / denom) =================
// 64x64 tile, BK=16, 256 threads, 4x4 microtile, double-buffered smem.
// Requires M%64==0, N%64==0, K%16==0 (true for all call sites).
template <int RELU, int DIV, int BIAS>
__global__ void __launch_bounds__(256) gemm64(
    const float* __restrict__ A, const float* __restrict__ W,
    const float* __restrict__ bias, const float* __restrict__ denom,
    float* __restrict__ C, int M, int N, int K,
    long long sA, long long sW, long long sC)
{
    __shared__ __align__(16) float As[2][16][64];
    __shared__ __align__(16) float Bs[2][16][64];

    const int tid = threadIdx.x;
    const int tx = tid & 15;      // 0..15 (cols)
    const int ty = tid >> 4;      // 0..15 (rows)
    const int bx = blockIdx.x, by = blockIdx.y, bz = blockIdx.z;

    A += (long long)bz * sA;
    W += (long long)bz * sW;
    C += (long long)bz * sC;

    const int row0 = by * 64, col0 = bx * 64;

    const int arow  = tid >> 2;   // 0..63
    const int acol4 = tid & 3;    // 0..3
    const int brow  = tid >> 4;   // 0..15
    const int bcol4 = tid & 15;   // 0..15

    const float* Aptr = A + (long long)(row0 + arow) * K + acol4 * 4;
    const float* Wptr = W + (long long)brow * N + col0 + bcol4 * 4;

    float4 aref = *(const float4*)Aptr;
    float4 bref = *(const float4*)Wptr;

    float acc[4][4];
#pragma unroll
    for (int i = 0; i < 4; i++)
#pragma unroll
        for (int j = 0; j < 4; j++) acc[i][j] = 0.f;

    const int nt = K / 16;

    // stage tile 0
    As[0][acol4 * 4 + 0][arow] = aref.x;
    As[0][acol4 * 4 + 1][arow] = aref.y;
    As[0][acol4 * 4 + 2][arow] = aref.z;
    As[0][acol4 * 4 + 3][arow] = aref.w;
    *(float4*)&Bs[0][brow][bcol4 * 4] = bref;
    __syncthreads();

    for (int kt = 0; kt < nt; kt++) {
        const int buf = kt & 1;
        if (kt + 1 < nt) {
            aref = *(const float4*)(Aptr + (kt + 1) * 16);
            bref = *(const float4*)(Wptr + (long long)(kt + 1) * 16 * N);
        }
#pragma unroll
        for (int kk = 0; kk < 16; kk++) {
            float4 av = *(const float4*)&As[buf][kk][ty * 4];
            float4 bv = *(const float4*)&Bs[buf][kk][tx * 4];
            acc[0][0] += av.x * bv.x; acc[0][1] += av.x * bv.y; acc[0][2] += av.x * bv.z; acc[0][3] += av.x * bv.w;
            acc[1][0] += av.y * bv.x; acc[1][1] += av.y * bv.y; acc[1][2] += av.y * bv.z; acc[1][3] += av.y * bv.w;
            acc[2][0] += av.z * bv.x; acc[2][1] += av.z * bv.y; acc[2][2] += av.z * bv.z; acc[2][3] += av.z * bv.w;
            acc[3][0] += av.w * bv.x; acc[3][1] += av.w * bv.y; acc[3][2] += av.w * bv.z; acc[3][3] += av.w * bv.w;
        }
        if (kt + 1 < nt) {
            const int nb = buf ^ 1;
            As[nb][acol4 * 4 + 0][arow] = aref.x;
            As[nb][acol4 * 4 + 1][arow] = aref.y;
            As[nb][acol4 * 4 + 2][arow] = aref.z;
            As[nb][acol4 * 4 + 3][arow] = aref.w;
            *(float4*)&Bs[nb][brow][bcol4 * 4] = bref;
        }
        __syncthreads();
    }

    // epilogue
#pragma unroll
    for (int i = 0; i < 4; i++) {
        const int r = row0 + ty * 4 + i;
        float inv = 1.f;
        if (DIV) inv = 1.f / denom[r];
        float4 o;
        o.x = acc[i][0]; o.y = acc[i][1]; o.z = acc[i][2]; o.w = acc[i][3];
        if (BIAS) {
            const float* bp = bias + col0 + tx * 4;
            o.x += bp[0]; o.y += bp[1]; o.z += bp[2]; o.w += bp[3];
        }
        if (DIV) { o.x *= inv; o.y *= inv; o.z *= inv; o.w *= inv; }
        if (RELU) {
            o.x = fmaxf(o.x, 0.f); o.y = fmaxf(o.y, 0.f);
            o.z = fmaxf(o.z, 0.f); o.w = fmaxf(o.w, 0.f);
        }
        *(float4*)(C + (long long)r * N + col0 + tx * 4) = o;
    }
}

// ================= fused attention: scores + rel bias + mask + softmax + head-mean
//                   + diag/row-mask + denom. Writes adj and denom, never (B,H,S,S). ====
// One block = 8 q-rows of one batch; 512 threads = one per k-column.
__global__ void __launch_bounds__(512, 2) attn_kernel(
    const float* __restrict__ qm, const float* __restrict__ km,
    const int* __restrict__ tok, const float* __restrict__ rel_emb,
    float* __restrict__ adj, float* __restrict__ denom)
{
    __shared__ __align__(16) float sQ[8][Dn];
    __shared__ __align__(16) float sQm[8][DKn];
    __shared__ float sR[8][257];
    __shared__ float sRed[16][8];
    __shared__ float sB[8];
    __shared__ int sTokQ[8];

    const int tid = threadIdx.x;
    const int b = blockIdx.x >> 6;          // S/8 = 64 blocks per batch
    const int q0 = (blockIdx.x & 63) * 8;
    const long long qbase = ((long long)b * Sn + q0) * Dn;

    // load 8 q rows (contiguous)
    for (int e = tid; e < 8 * Dn; e += 512) ((float*)sQ)[e] = qm[qbase + e];
    if (tid < 8) sTokQ[tid] = tok[b * Sn + q0 + tid];
    __syncthreads();

    // head-mean of q
    for (int e = tid; e < 8 * DKn; e += 512) {
        const int qq = e / DKn, d = e % DKn;
        float s = 0.f;
#pragma unroll
        for (int h = 0; h < Hn; h++) s += sQ[qq][h * DKn + d];
        sQm[qq][d] = s * 0.125f;
    }
    __syncthreads();

    // r[q][j] = q_mean[q] . rel_emb[j]
    for (int e = tid; e < 8 * 257; e += 512) {
        const int qq = e / 257, j = e % 257;
        const float4* rp = (const float4*)(rel_emb + j * DKn);
        const float4* qp = (const float4*)sQm[qq];
        float s = 0.f;
#pragma unroll
        for (int d4 = 0; d4 < DKn / 4; d4++) {
            float4 rv = rp[d4], qv = qp[d4];
            s += rv.x * qv.x + rv.y * qv.y + rv.z * qv.z + rv.w * qv.w;
        }
        sR[qq][j] = s;
    }
    __syncthreads();

    const int kcol = tid;
    const bool kz = (tok[b * Sn + kcol] == 0);
    const float4* krow = (const float4*)(km + ((long long)b * Sn + kcol) * Dn);
    const float scale = 0.10206207261596577f;  // 1/sqrt(96)
    const int lane = tid & 31, wid = tid >> 5;

    float padj[8];
#pragma unroll
    for (int qq = 0; qq < 8; qq++) padj[qq] = 0.f;

    for (int h = 0; h < Hn; h++) {
        float sc[8];
#pragma unroll
        for (int qq = 0; qq < 8; qq++) sc[qq] = 0.f;
        const float4* kh = krow + h * (DKn / 4);
#pragma unroll
        for (int d4 = 0; d4 < DKn / 4; d4++) {
            const float4 kv = kh[d4];
#pragma unroll
            for (int qq = 0; qq < 8; qq++) {
                const float4 qv = *(const float4*)&sQ[qq][h * DKn + d4 * 4];
                sc[qq] += kv.x * qv.x + kv.y * qv.y + kv.z * qv.z + kv.w * qv.w;
            }
        }
#pragma unroll
        for (int qq = 0; qq < 8; qq++) {
            int dist = kcol - (q0 + qq);
            dist = min(max(dist, -128), 128) + 128;
            const float s = (sc[qq] + sR[qq][dist]) * scale;
            sc[qq] = kz ? -1e9f : s;
        }
        // block max (vector of 8)
        float red[8];
#pragma unroll
        for (int qq = 0; qq < 8; qq++) red[qq] = sc[qq];
#pragma unroll
        for (int off = 16; off > 0; off >>= 1)
#pragma unroll
            for (int qq = 0; qq < 8; qq++)
                red[qq] = fmaxf(red[qq], __shfl_xor_sync(0xffffffffu, red[qq], off));
        if (lane == 0)
#pragma unroll
            for (int qq = 0; qq < 8; qq++) sRed[wid][qq] = red[qq];
        __syncthreads();
        if (tid < 8) {
            float v = sRed[0][tid];
#pragma unroll
            for (int w = 1; w < 16; w++) v = fmaxf(v, sRed[w][tid]);
            sB[tid] = v;
        }
        __syncthreads();
        float ex[8];
#pragma unroll
        for (int qq = 0; qq < 8; qq++) ex[qq] = expf(sc[qq] - sB[qq]);
        // block sum
#pragma unroll
        for (int qq = 0; qq < 8; qq++) red[qq] = ex[qq];
#pragma unroll
        for (int off = 16; off > 0; off >>= 1)
#pragma unroll
            for (int qq = 0; qq < 8; qq++)
                red[qq] += __shfl_xor_sync(0xffffffffu, red[qq], off);
        if (lane == 0)
#pragma unroll
            for (int qq = 0; qq < 8; qq++) sRed[wid][qq] = red[qq];
        __syncthreads();
        if (tid < 8) {
            float v = 0.f;
#pragma unroll
            for (int w = 0; w < 16; w++) v += sRed[w][tid];
            sB[tid] = v;
        }
        __syncthreads();
#pragma unroll
        for (int qq = 0; qq < 8; qq++) padj[qq] += (ex[qq] / sB[qq]) * 0.125f;
        __syncthreads();  // protect sRed/sB before next head overwrites
    }

    // diag -> 1, row mask, write adj, compute denom
    float rowv[8];
#pragma unroll
    for (int qq = 0; qq < 8; qq++) {
        float v = padj[qq];
        if (kcol == q0 + qq) v = 1.0f;
        if (sTokQ[qq] == 0) v = 0.0f;
        rowv[qq] = v;
        adj[((long long)b * Sn + q0 + qq) * Sn + kcol] = v;
    }
    float red[8];
#pragma unroll
    for (int qq = 0; qq < 8; qq++) red[qq] = rowv[qq];
#pragma unroll
    for (int off = 16; off > 0; off >>= 1)
#pragma unroll
        for (int qq = 0; qq < 8; qq++)
            red[qq] += __shfl_xor_sync(0xffffffffu, red[qq], off);
    if (lane == 0)
#pragma unroll
        for (int qq = 0; qq < 8; qq++) sRed[wid][qq] = red[qq];
    __syncthreads();
    if (tid < 8) {
        float v = 0.f;
#pragma unroll
        for (int w = 0; w < 16; w++) v += sRed[w][tid];
        denom[b * Sn + q0 + tid] = v + 1.0f;
    }
}

// ================= small elementwise / pooling / gating kernels =================
__global__ void combine_kernel(const float* __restrict__ h0, const float* __restrict__ h1,
                               const float* __restrict__ sw, float* __restrict__ out)
{
    const int i = blockIdx.x * 256 + threadIdx.x;
    const float s0 = sw[0], s1 = sw[1];
    const float m = fmaxf(s0, s1);
    const float e0 = expf(s0 - m), e1 = expf(s1 - m);
    const float inv = 1.f / (e0 + e1);
    out[i] = (e0 * inv) * h0[i] + (e1 * inv) * h1[i];
}

__global__ void pool_kernel(const float* __restrict__ x, float* __restrict__ pool)
{
    const int b = blockIdx.y;
    const int d = blockIdx.x * 128 + threadIdx.x;
    const float* xp = x + (long long)b * Sn * Dn + d;
    float sm = 0.f, mx = -3.402823466e38f;
    for (int s = 0; s < Sn; s++) {
        const float v = xp[(long long)s * Dn];
        sm += v;
        mx = fmaxf(mx, v);
    }
    pool[b * (2 * Dn) + d] = sm * (1.f / Sn);
    pool[b * (2 * Dn) + Dn + d] = mx;
}

// out[b,n] = act(sum_k in[b,k]*W[k,n] + bias[n]); ACT: 0=none, 1=sigmoid
template <int ACT>
__global__ void rowmat_kernel(const float* __restrict__ in, const float* __restrict__ W,
                              const float* __restrict__ bias, float* __restrict__ out,
                              int K, int N)
{
    __shared__ float sIn[2 * Dn];
    const int b = blockIdx.y;
    const int n = blockIdx.x * 128 + threadIdx.x;
    for (int e = threadIdx.x; e < K; e += 128) sIn[e] = in[b * K + e];
    __syncthreads();
    float acc = bias[n];
#pragma unroll 4
    for (int k = 0; k < K; k++) acc += sIn[k] * W[(long long)k * N + n];
    if (ACT) acc = 1.f / (1.f + expf(-acc));
    out[b * N + n] = acc;
}

__global__ void final_kernel(float* __restrict__ x, const float* __restrict__ gate,
                             const float* __restrict__ gc)
{
    const int i = blockIdx.x * 256 + threadIdx.x;
    const int d = i % Dn;
    const int b = i / (Sn * Dn);
    x[i] += gate[b * Dn + d] * gc[b * Dn + d];
}

// ================= launch =================
extern "C" void kernel_launch(void* const* d_in, const int* in_sizes, int n_in,
                              void* d_out, int out_size)
{
    // input order per setup_inputs; seq_lens may appear as a size-1 scalar at idx 2
    int o = (n_in >= 3 && in_sizes[2] == 1) ? 1 : 0;
    const float* inputs = (const float*)d_in[0];
    const int*   tok    = (const int*)d_in[1];
    const float* Wq  = (const float*)d_in[2 + o];
    const float* bq  = (const float*)d_in[3 + o];
    const float* Wk  = (const float*)d_in[4 + o];
    const float* bk  = (const float*)d_in[5 + o];
    const float* rel = (const float*)d_in[6 + o];
    const float* W0  = (const float*)d_in[7 + o];
    const float* b0  = (const float*)d_in[8 + o];
    const float* W1  = (const float*)d_in[9 + o];
    const float* b1  = (const float*)d_in[10 + o];
    const float* scw = (const float*)d_in[11 + o];
    const float* Wf  = (const float*)d_in[12 + o];
    const float* bf  = (const float*)d_in[13 + o];
    const float* Wfc = (const float*)d_in[14 + o];
    const float* bfc = (const float*)d_in[15 + o];
    const float* Wg  = (const float*)d_in[16 + o];
    const float* bg  = (const float*)d_in[17 + o];

    float* out = (float*)d_out;                      // (B,S,D) outputs
    float* adj = out + (size_t)Bn * Sn * Dn;         // (B,S,S) adjacency

    float *q, *k, *ax, *h0, *h1, *den, *pool, *gc, *gate;
    cudaGetSymbolAddress((void**)&q, g_q);
    cudaGetSymbolAddress((void**)&k, g_k);
    cudaGetSymbolAddress((void**)&ax, g_ax);
    cudaGetSymbolAddress((void**)&h0, g_h0);
    cudaGetSymbolAddress((void**)&h1, g_h1);
    cudaGetSymbolAddress((void**)&den, g_denom);
    cudaGetSymbolAddress((void**)&pool, g_pool);
    cudaGetSymbolAddress((void**)&gc, g_gc);
    cudaGetSymbolAddress((void**)&gate, g_gate);

    const dim3 blk(256);
    const dim3 g_flat(Dn / 64, (Bn * Sn) / 64, 1);   // 12 x 128
    const dim3 g_bmm(Dn / 64, Sn / 64, Bn);          // 12 x 8 x 16

    // Q/K projections
    gemm64<0, 0, 1><<<g_flat, blk>>>(inputs, Wq, bq, nullptr, q, Bn * Sn, Dn, Dn, 0, 0, 0);
    gemm64<0, 0, 1><<<g_flat, blk>>>(inputs, Wk, bk, nullptr, k, Bn * Sn, Dn, Dn, 0, 0, 0);

    // fused attention -> adj, denom
    attn_kernel<<<Bn * (Sn / 8), 512>>>(q, k, tok, rel, adj, den);

    // GCN layer 0
    gemm64<0, 0, 0><<<g_bmm, blk>>>(adj, inputs, nullptr, nullptr, ax, Sn, Dn, Sn,
                                    (long long)Sn * Sn, (long long)Sn * Dn, (long long)Sn * Dn);
    gemm64<1, 1, 1><<<g_flat, blk>>>(ax, W0, b0, den, h0, Bn * Sn, Dn, Dn, 0, 0, 0);

    // GCN layer 1
    gemm64<0, 0, 0><<<g_bmm, blk>>>(adj, h0, nullptr, nullptr, ax, Sn, Dn, Sn,
                                    (long long)Sn * Sn, (long long)Sn * Dn, (long long)Sn * Dn);
    gemm64<1, 1, 1><<<g_flat, blk>>>(ax, W1, b1, den, h1, Bn * Sn, Dn, Dn, 0, 0, 0);

    // fusion + Wf  (x written directly into d_out)
    combine_kernel<<<(Bn * Sn * Dn) / 256, 256>>>(h0, h1, scw, ax);
    gemm64<0, 0, 1><<<g_flat, blk>>>(ax, Wf, bf, nullptr, out, Bn * Sn, Dn, Dn, 0, 0, 0);

    // global context gating
    pool_kernel<<<dim3(Dn / 128, Bn), 128>>>(out, pool);
    rowmat_kernel<0><<<dim3(Dn / 128, Bn), 128>>>(pool, Wfc, bfc, gc, 2 * Dn, Dn);
    rowmat_kernel<1><<<dim3(Dn / 128, Bn), 128>>>(gc, Wg, bg, gate, Dn, Dn);
    final_kernel<<<(Bn * Sn * Dn) / 256, 256>>>(out, gate, gc);
}